// round 12
// baseline (speedup 1.0000x reference)
#include <cuda_runtime.h>
#include <cuda_bf16.h>
#include <cstdint>
#include <cstddef>
#include <math.h>

// Problem constants (fixed by the reference: B=8, N=4096, NITER=4)
constexpr int B = 8;
constexpr int N = 4096;
constexpr int NITER = 4;
constexpr int BN = B * N;

constexpr int NCHUNK = 32;          // b-dimension split
constexpr int CB = N / NCHUNK;      // 128 P-rows per chunk
constexpr int TILE_A = 128;         // output columns per block
constexpr int NTILE = N / TILE_A;   // 32 a-tiles
constexpr int BLOCK_A = 128;        // 32 col-quads x 4 batch-pairs

// Static scratch (no allocations allowed)
__device__ float g_part[(size_t)NCHUNK * BN];     // 4 MB partial sums
__device__ float g_pred[BN];                      // current pred between iterations
__device__ unsigned short g_Pb[(size_t)N * N];    // 32 MB bf16 copy of P (built in iter 1)

using ull = unsigned long long;

__device__ __forceinline__ ull pk2(float x) {
    ull r; asm("mov.b64 %0, {%1, %1};" : "=l"(r) : "f"(x)); return r;
}
__device__ __forceinline__ ull pk2u(unsigned w) {        // dup a raw f32 bit pattern
    ull r; asm("mov.b64 %0, {%1, %1};" : "=l"(r) : "r"(w)); return r;
}
__device__ __forceinline__ ull fma2(ull a, ull b, ull c) {
    ull d; asm("fma.rn.f32x2 %0, %1, %2, %3;" : "=l"(d) : "l"(a), "l"(b), "l"(c)); return d;
}
__device__ __forceinline__ void upk2(ull v, float& lo, float& hi) {
    asm("mov.b64 {%0, %1}, %2;" : "=f"(lo), "=f"(hi) : "l"(v));
}
__device__ __forceinline__ unsigned bf16x2_rn(float hi, float lo) {
    unsigned r; asm("cvt.rn.bf16x2.f32 %0, %1, %2;" : "=r"(r) : "f"(hi), "f"(lo)); return r;
}

// ---------------- Kernel A, iteration 1 (fp32 P; also emits bf16 P copy) -----
// Grid (NTILE=32, NCHUNK=32) = 1024 blocks x 128 threads.
// Thread (q,p): col quad q (4 consecutive a), batch pair p; 4-lane warp-dedup of
// the P float4. p==0 lanes additionally convert their float4 -> 4 bf16 (8B store);
// block (tile,chunk) exclusively owns that P sub-tile, so coverage is exact.
__global__ void __launch_bounds__(BLOCK_A, 8) propA_f32cvt(
    const float* __restrict__ P, const float* __restrict__ pred0)
{
    __shared__ ull s_p2[CB * 4];                  // pred chunk, batch-paired (4 KB)
    float* s_f = reinterpret_cast<float*>(s_p2);

    const int tid = threadIdx.x;
    const int c = blockIdx.y;
    const int b0 = c * CB;

#pragma unroll
    for (int j = 0; j < (CB * B) / BLOCK_A; j++) {   // 8 per thread
        int idx = j * BLOCK_A + tid;
        int i = idx >> 7;
        int b = idx & (CB - 1);
        s_f[b * 8 + i] = pred0[i * N + b0 + b];
    }
    __syncthreads();

    const int q = tid >> 2;
    const int p = tid & 3;
    const int a0 = blockIdx.x * TILE_A + q * 4;
    const float4* __restrict__ p4 =
        reinterpret_cast<const float4*>(P + (size_t)b0 * N) + (a0 >> 2);
    uint2* __restrict__ pb_out =
        reinterpret_cast<uint2*>(g_Pb + (size_t)b0 * N + a0);

    ull acc0 = 0, acc1 = 0, acc2 = 0, acc3 = 0;

#pragma unroll 4
    for (int b = 0; b < CB; b++) {
        float4 pv = __ldg(&p4[(size_t)b * (N >> 2)]);
        if (p == 0) {
            uint2 w;
            w.x = bf16x2_rn(pv.y, pv.x);   // lo16 = col a0, hi16 = col a0+1
            w.y = bf16x2_rn(pv.w, pv.z);
            pb_out[(size_t)b * (N >> 2)] = w;
        }
        ull np = s_p2[b * 4 + p];
        acc0 = fma2(pk2(pv.x), np, acc0);
        acc1 = fma2(pk2(pv.y), np, acc1);
        acc2 = fma2(pk2(pv.z), np, acc2);
        acc3 = fma2(pk2(pv.w), np, acc3);
    }

    float lo0, hi0, lo1, hi1, lo2, hi2, lo3, hi3;
    upk2(acc0, lo0, hi0); upk2(acc1, lo1, hi1);
    upk2(acc2, lo2, hi2); upk2(acc3, lo3, hi3);
    float* outc = g_part + (size_t)c * BN;
    *reinterpret_cast<float4*>(outc + (size_t)(2 * p) * N + a0) =
        make_float4(lo0, lo1, lo2, lo3);
    *reinterpret_cast<float4*>(outc + (size_t)(2 * p + 1) * N + a0) =
        make_float4(hi0, hi1, hi2, hi3);
}

// ---------------- Kernel A, iterations 2..4 (bf16 P) -------------------------
// Same structure; loads uint2 (4 bf16) and expands bf16->f32 with PRMT (exact:
// f32 bits = bf16 bits << 16). PRMT rides the idle alu pipe next to the fma pipe.
__global__ void __launch_bounds__(BLOCK_A, 8) propA_bf16()
{
    __shared__ ull s_p2[CB * 4];
    float* s_f = reinterpret_cast<float*>(s_p2);

    const int tid = threadIdx.x;
    const int c = blockIdx.y;
    const int b0 = c * CB;

#pragma unroll
    for (int j = 0; j < (CB * B) / BLOCK_A; j++) {
        int idx = j * BLOCK_A + tid;
        int i = idx >> 7;
        int b = idx & (CB - 1);
        s_f[b * 8 + i] = g_pred[i * N + b0 + b];
    }
    __syncthreads();

    const int q = tid >> 2;
    const int p = tid & 3;
    const int a0 = blockIdx.x * TILE_A + q * 4;
    const uint2* __restrict__ pb =
        reinterpret_cast<const uint2*>(g_Pb + (size_t)b0 * N + a0);

    ull acc0 = 0, acc1 = 0, acc2 = 0, acc3 = 0;

#pragma unroll 8
    for (int b = 0; b < CB; b++) {
        uint2 pv = __ldg(&pb[(size_t)b * (N >> 2)]);
        // expand 4 bf16 -> 4 f32 bit patterns (byte shuffle, exact)
        unsigned w0 = __byte_perm(pv.x, 0, 0x1044);   // {0,0, b0,b1} = bf16_0 << 16
        unsigned w1 = __byte_perm(pv.x, 0, 0x3244);   // {0,0, b2,b3} = bf16_1 << 16
        unsigned w2 = __byte_perm(pv.y, 0, 0x1044);
        unsigned w3 = __byte_perm(pv.y, 0, 0x3244);
        ull np = s_p2[b * 4 + p];
        acc0 = fma2(pk2u(w0), np, acc0);
        acc1 = fma2(pk2u(w1), np, acc1);
        acc2 = fma2(pk2u(w2), np, acc2);
        acc3 = fma2(pk2u(w3), np, acc3);
    }

    float lo0, hi0, lo1, hi1, lo2, hi2, lo3, hi3;
    upk2(acc0, lo0, hi0); upk2(acc1, lo1, hi1);
    upk2(acc2, lo2, hi2); upk2(acc3, lo3, hi3);
    float* outc = g_part + (size_t)c * BN;
    *reinterpret_cast<float4*>(outc + (size_t)(2 * p) * N + a0) =
        make_float4(lo0, lo1, lo2, lo3);
    *reinterpret_cast<float4*>(outc + (size_t)(2 * p + 1) * N + a0) =
        make_float4(hi0, hi1, hi2, hi3);
}

// ---------------- Kernel C: combine + exp + seed clamp (unchanged from R10) --
__global__ void __launch_bounds__(256) propC(const int2* __restrict__ seed, int nseeds,
                                             float* __restrict__ final_out) {
    __shared__ int s_flat[128];
    const int tid = threadIdx.x;
    if (tid < nseeds) {
        int2 s = seed[tid];
        s_flat[tid] = s.x * N + s.y;
    }
    __syncthreads();

    const int g2 = blockIdx.x * 256 + tid;
    const int o = g2 >> 1;
    const int half = g2 & 1;
    const int cbase = half * 16;

    float a0 = 0.f, a1 = 0.f, a2 = 0.f, a3 = 0.f;
    float a4 = 0.f, a5 = 0.f, a6 = 0.f, a7 = 0.f;
#pragma unroll
    for (int c = 0; c < 16; c += 8) {
        a0 += __ldg(&g_part[(size_t)(cbase + c + 0) * BN + o]);
        a1 += __ldg(&g_part[(size_t)(cbase + c + 1) * BN + o]);
        a2 += __ldg(&g_part[(size_t)(cbase + c + 2) * BN + o]);
        a3 += __ldg(&g_part[(size_t)(cbase + c + 3) * BN + o]);
        a4 += __ldg(&g_part[(size_t)(cbase + c + 4) * BN + o]);
        a5 += __ldg(&g_part[(size_t)(cbase + c + 5) * BN + o]);
        a6 += __ldg(&g_part[(size_t)(cbase + c + 6) * BN + o]);
        a7 += __ldg(&g_part[(size_t)(cbase + c + 7) * BN + o]);
    }
    float s = ((a0 + a1) + (a2 + a3)) + ((a4 + a5) + (a6 + a7));
    s += __shfl_xor_sync(0xffffffffu, s, 1);

    if (half == 0) {
        float v = 1.0f - __expf(-s);
        for (int k = 0; k < nseeds; k++)
            if (s_flat[k] == o) v = 1.0f;
        g_pred[o] = v;
        if (final_out) final_out[o] = v;
    }
}

extern "C" void kernel_launch(void* const* d_in, const int* in_sizes, int n_in,
                              void* d_out, int out_size) {
    const float* preds = (const float*)d_in[0];      // [B, N] fp32
    const float* P = (const float*)d_in[1];          // [N, N] fp32, P[b*N + a]
    const int2* seed = (const int2*)d_in[2];         // [NSEEDS, 2] int32 (b, n)
    int nseeds = in_sizes[2] / 2;
    if (nseeds > 128) nseeds = 128;
    float* out = (float*)d_out;

    dim3 gridA(NTILE, NCHUNK);      // (32, 32) = 1024 blocks
    dim3 gridC(2 * BN / 256);       // 256 blocks

    for (int t = 0; t < NITER; t++) {
        if (t == 0)
            propA_f32cvt<<<gridA, BLOCK_A>>>(P, preds);
        else
            propA_bf16<<<gridA, BLOCK_A>>>();
        propC<<<gridC, 256>>>(seed, nseeds, (t == NITER - 1) ? out : nullptr);
    }
}

// round 14
// speedup vs baseline: 1.2474x; 1.2474x over previous
#include <cuda_runtime.h>
#include <cstdint>
#include <cstddef>
#include <math.h>

// Problem constants (fixed by the reference: B=8, N=4096, NITER=4)
constexpr int B = 8;
constexpr int N = 4096;
constexpr int NITER = 4;
constexpr int BN = B * N;

constexpr int NCHUNK = 64;          // b-dimension split
constexpr int CB = N / NCHUNK;      // 64 P-rows per chunk
constexpr int TILE_A = 512;         // output columns per block
constexpr int NTILE = N / TILE_A;   // 8 a-tiles
constexpr int BLOCK_A = 128;        // threads: each owns 4 cols x 8 batches

// Static scratch (no allocations allowed)
__device__ float g_part[(size_t)NCHUNK * BN];   // 8 MB partial sums
__device__ float g_pred[BN];                    // current pred between iterations

using ull = unsigned long long;

__device__ __forceinline__ ull pk2(float x) {
    ull r; asm("mov.b64 %0, {%1, %1};" : "=l"(r) : "f"(x)); return r;
}
__device__ __forceinline__ ull fma2(ull a, ull b, ull c) {
    ull d; asm("fma.rn.f32x2 %0, %1, %2, %3;" : "=l"(d) : "l"(a), "l"(b), "l"(c)); return d;
}
__device__ __forceinline__ void upk2(ull v, float& lo, float& hi) {
    asm("mov.b64 {%0, %1}, %2;" : "=f"(lo), "=f"(hi) : "l"(v));
}

// Kernel A: partial sums S_c[i,a] = sum_{b in chunk c} pred[i,b] * P[b,a].
// Grid (NTILE=8, NCHUNK=64) = 512 blocks x 128 threads.
// Thread: 4 consecutive a-columns x ALL 8 batches. Every lane loads a DISTINCT
// P float4 -> each warp-LDG covers 512B (max), 4x fewer LDG instructions than
// the quad-dedup layout (which was LSU-issue-bound).
__global__ void __launch_bounds__(BLOCK_A, 6) propA(
    const float* __restrict__ P, const float* __restrict__ pred0, int use_ext)
{
    __shared__ ull s_p2[CB * 4];                  // pred chunk, batch-paired (2 KB)
    float* s_f = reinterpret_cast<float*>(s_p2);  // s_f[b*8 + i] = pred[i][b0+b]

    const int tid = threadIdx.x;
    const int c = blockIdx.y;
    const int b0 = c * CB;
    const float* __restrict__ pred = use_ext ? pred0 : g_pred;

#pragma unroll
    for (int j = 0; j < (CB * B) / BLOCK_A; j++) {   // 4 per thread
        int idx = j * BLOCK_A + tid;
        int i = idx >> 6;          // batch 0..7
        int b = idx & (CB - 1);    // local row 0..63
        s_f[b * 8 + i] = pred[i * N + b0 + b];
    }
    __syncthreads();

    const int a0 = blockIdx.x * TILE_A + tid * 4;
    const float4* __restrict__ p4 =
        reinterpret_cast<const float4*>(P + (size_t)b0 * N) + (a0 >> 2);

    // acc[ai][p]: column a0+ai, batch pair p (batches 2p, 2p+1)
    ull acc[4][4];
#pragma unroll
    for (int ai = 0; ai < 4; ai++)
#pragma unroll
        for (int p = 0; p < 4; p++) acc[ai][p] = 0ULL;

#pragma unroll 2
    for (int b = 0; b < CB; b++) {
        float4 pv = __ldg(&p4[(size_t)b * (N >> 2)]);
        ull P2[4] = { pk2(pv.x), pk2(pv.y), pk2(pv.z), pk2(pv.w) };
        ull np[4];
#pragma unroll
        for (int p = 0; p < 4; p++) np[p] = s_p2[b * 4 + p];   // 32B broadcast
#pragma unroll
        for (int ai = 0; ai < 4; ai++)
#pragma unroll
            for (int p = 0; p < 4; p++)
                acc[ai][p] = fma2(P2[ai], np[p], acc[ai][p]);
    }

    // Store: for each batch pair p, two float4 rows (lo batch, hi batch).
    float* outc = g_part + (size_t)c * BN;
#pragma unroll
    for (int p = 0; p < 4; p++) {
        float lo[4], hi[4];
#pragma unroll
        for (int ai = 0; ai < 4; ai++) upk2(acc[ai][p], lo[ai], hi[ai]);
        *reinterpret_cast<float4*>(outc + (size_t)(2 * p) * N + a0) =
            make_float4(lo[0], lo[1], lo[2], lo[3]);
        *reinterpret_cast<float4*>(outc + (size_t)(2 * p + 1) * N + a0) =
            make_float4(hi[0], hi[1], hi[2], hi[3]);
    }
}

// Kernel C: sum the 64 planes, v = 1 - exp(-S), seed clamp, write pred (+ out).
// 4 threads per output scalar (sub k sums planes 16k..16k+15), 8 independent
// accumulator chains each, then 2-step shfl butterfly combine.
__global__ void __launch_bounds__(256) propC(const int2* __restrict__ seed, int nseeds,
                                             float* __restrict__ final_out) {
    __shared__ int s_flat[128];
    const int tid = threadIdx.x;
    if (tid < nseeds) {
        int2 s = seed[tid];
        s_flat[tid] = s.x * N + s.y;
    }
    __syncthreads();

    const int g4 = blockIdx.x * 256 + tid;
    const int o = g4 >> 2;             // output index
    const int sub = g4 & 3;            // plane-group
    const int cbase = sub * 16;

    float a0 = 0.f, a1 = 0.f, a2 = 0.f, a3 = 0.f;
    float a4 = 0.f, a5 = 0.f, a6 = 0.f, a7 = 0.f;
#pragma unroll
    for (int c = 0; c < 16; c += 8) {
        a0 += __ldg(&g_part[(size_t)(cbase + c + 0) * BN + o]);
        a1 += __ldg(&g_part[(size_t)(cbase + c + 1) * BN + o]);
        a2 += __ldg(&g_part[(size_t)(cbase + c + 2) * BN + o]);
        a3 += __ldg(&g_part[(size_t)(cbase + c + 3) * BN + o]);
        a4 += __ldg(&g_part[(size_t)(cbase + c + 4) * BN + o]);
        a5 += __ldg(&g_part[(size_t)(cbase + c + 5) * BN + o]);
        a6 += __ldg(&g_part[(size_t)(cbase + c + 6) * BN + o]);
        a7 += __ldg(&g_part[(size_t)(cbase + c + 7) * BN + o]);
    }
    float s = ((a0 + a1) + (a2 + a3)) + ((a4 + a5) + (a6 + a7));
    s += __shfl_xor_sync(0xffffffffu, s, 1);
    s += __shfl_xor_sync(0xffffffffu, s, 2);

    if (sub == 0) {
        float v = 1.0f - __expf(-s);
        for (int k = 0; k < nseeds; k++)
            if (s_flat[k] == o) v = 1.0f;
        g_pred[o] = v;
        if (final_out) final_out[o] = v;
    }
}

extern "C" void kernel_launch(void* const* d_in, const int* in_sizes, int n_in,
                              void* d_out, int out_size) {
    const float* preds = (const float*)d_in[0];      // [B, N] fp32
    const float* P = (const float*)d_in[1];          // [N, N] fp32, P[b*N + a]
    const int2* seed = (const int2*)d_in[2];         // [NSEEDS, 2] int32 (b, n)
    int nseeds = in_sizes[2] / 2;
    if (nseeds > 128) nseeds = 128;
    float* out = (float*)d_out;

    dim3 gridA(NTILE, NCHUNK);      // (8, 64) = 512 blocks
    dim3 gridC(4 * BN / 256);       // 512 blocks

    for (int t = 0; t < NITER; t++) {
        propA<<<gridA, BLOCK_A>>>(P, preds, t == 0 ? 1 : 0);
        propC<<<gridC, 256>>>(seed, nseeds, (t == NITER - 1) ? out : nullptr);
    }
}

// round 15
// speedup vs baseline: 1.2999x; 1.0420x over previous
#include <cuda_runtime.h>
#include <cstdint>
#include <cstddef>
#include <math.h>

// Problem constants (fixed by the reference: B=8, N=4096, NITER=4)
constexpr int B = 8;
constexpr int N = 4096;
constexpr int NITER = 4;
constexpr int BN = B * N;
constexpr int NPAIR = BN / 2;       // batch-pair elements per plane (4*N)

constexpr int NCHUNK = 64;          // b-dimension split
constexpr int CB = N / NCHUNK;      // 64 P-rows per chunk
constexpr int TILE_A = 512;         // output columns per block
constexpr int NTILE = N / TILE_A;   // 8 a-tiles
constexpr int BLOCK_A = 128;        // threads: each owns 4 cols x 8 batches

// Static scratch (no allocations allowed)
__device__ unsigned g_partb[(size_t)NCHUNK * NPAIR];  // 4 MB bf16x2 partial sums
__device__ float g_pred[BN];                          // current pred between iterations

using ull = unsigned long long;

__device__ __forceinline__ ull pk2(float x) {
    ull r; asm("mov.b64 %0, {%1, %1};" : "=l"(r) : "f"(x)); return r;
}
__device__ __forceinline__ ull fma2(ull a, ull b, ull c) {
    ull d; asm("fma.rn.f32x2 %0, %1, %2, %3;" : "=l"(d) : "l"(a), "l"(b), "l"(c)); return d;
}
// f32x2 (lo,hi) -> packed bf16x2 (lo16=lo, hi16=hi)
__device__ __forceinline__ unsigned cvt_pair_bf16(ull v) {
    float lo, hi;
    asm("mov.b64 {%0, %1}, %2;" : "=f"(lo), "=f"(hi) : "l"(v));
    unsigned r;
    asm("cvt.rn.bf16x2.f32 %0, %1, %2;" : "=r"(r) : "f"(hi), "f"(lo));
    return r;
}

// Kernel A: partial sums S_c[i,a] = sum_{b in chunk c} pred[i,b] * P[b,a].
// Grid (NTILE=8, NCHUNK=64) = 512 blocks x 128 threads.
// Thread: 4 consecutive a-columns x ALL 8 batches; distinct-lane P float4 loads
// (512B per warp-LDG; LSU-issue minimal). Partials stored as bf16x2 batch pairs:
// plane c layout = [pair p][col a] (uint32 each), 64 KB per plane.
__global__ void __launch_bounds__(BLOCK_A, 6) propA(
    const float* __restrict__ P, const float* __restrict__ pred0, int use_ext)
{
    __shared__ ull s_p2[CB * 4];                  // pred chunk, batch-paired (2 KB)
    float* s_f = reinterpret_cast<float*>(s_p2);  // s_f[b*8 + i] = pred[i][b0+b]

    const int tid = threadIdx.x;
    const int c = blockIdx.y;
    const int b0 = c * CB;
    const float* __restrict__ pred = use_ext ? pred0 : g_pred;

#pragma unroll
    for (int j = 0; j < (CB * B) / BLOCK_A; j++) {   // 4 per thread
        int idx = j * BLOCK_A + tid;
        int i = idx >> 6;          // batch 0..7
        int b = idx & (CB - 1);    // local row 0..63
        s_f[b * 8 + i] = pred[i * N + b0 + b];
    }
    __syncthreads();

    const int a0 = blockIdx.x * TILE_A + tid * 4;
    const float4* __restrict__ p4 =
        reinterpret_cast<const float4*>(P + (size_t)b0 * N) + (a0 >> 2);

    // acc[ai][p]: column a0+ai, batch pair p (batches 2p, 2p+1)
    ull acc[4][4];
#pragma unroll
    for (int ai = 0; ai < 4; ai++)
#pragma unroll
        for (int p = 0; p < 4; p++) acc[ai][p] = 0ULL;

#pragma unroll 2
    for (int b = 0; b < CB; b++) {
        float4 pv = __ldg(&p4[(size_t)b * (N >> 2)]);
        ull P2[4] = { pk2(pv.x), pk2(pv.y), pk2(pv.z), pk2(pv.w) };
        ull np[4];
#pragma unroll
        for (int p = 0; p < 4; p++) np[p] = s_p2[b * 4 + p];   // 32B broadcast
#pragma unroll
        for (int ai = 0; ai < 4; ai++)
#pragma unroll
            for (int p = 0; p < 4; p++)
                acc[ai][p] = fma2(P2[ai], np[p], acc[ai][p]);
    }

    // Store bf16x2 partials: for each pair p, one uint4 (4 cols).
    unsigned* outc = g_partb + (size_t)c * NPAIR;
#pragma unroll
    for (int p = 0; p < 4; p++) {
        uint4 w;
        w.x = cvt_pair_bf16(acc[0][p]);
        w.y = cvt_pair_bf16(acc[1][p]);
        w.z = cvt_pair_bf16(acc[2][p]);
        w.w = cvt_pair_bf16(acc[3][p]);
        *reinterpret_cast<uint4*>(outc + (size_t)p * N + a0) = w;
    }
}

// Kernel C: sum the 64 bf16x2 planes per batch-pair, v = 1 - exp(-S), seed clamp,
// write pred (+ out). 8 threads per pair (sub k sums planes 8k..8k+7), PRMT unpack
// (exact bf16->f32), 3-step shfl butterfly, sub==0 writes BOTH batch outputs.
// Seed clamp via per-block smem bitmap (no per-thread 80-compare loop).
// Grid = 8*NPAIR/256 = 512 blocks x 256.
__global__ void __launch_bounds__(256) propC(const int2* __restrict__ seed, int nseeds,
                                             float* __restrict__ final_out) {
    __shared__ unsigned char s_seed[64];   // [local_pair][half]
    const int tid = threadIdx.x;
    const int op0 = blockIdx.x * 32;       // first pair index owned by this block
    if (tid < 64) s_seed[tid] = 0;
    __syncthreads();
    if (tid < nseeds) {
        int2 s = seed[tid];
        int op = (s.x >> 1) * N + s.y;     // pair index of this seed
        int local = op - op0;
        if (local >= 0 && local < 32) s_seed[local * 2 + (s.x & 1)] = 1;
    }
    __syncthreads();

    const int g = blockIdx.x * 256 + tid;
    const int op = g >> 3;                 // pair index: p*N + a
    const int sub = g & 7;                 // plane-group
    const unsigned* __restrict__ pp = g_partb + op + (size_t)(sub * 8) * NPAIR;

    float lo = 0.f, hi = 0.f;
#pragma unroll
    for (int c = 0; c < 8; c++) {
        unsigned w = __ldg(&pp[(size_t)c * NPAIR]);
        lo += __uint_as_float(__byte_perm(w, 0, 0x1044));   // bf16 lo << 16
        hi += __uint_as_float(__byte_perm(w, 0, 0x3244));   // bf16 hi << 16
    }
#pragma unroll
    for (int m = 1; m < 8; m <<= 1) {
        lo += __shfl_xor_sync(0xffffffffu, lo, m);
        hi += __shfl_xor_sync(0xffffffffu, hi, m);
    }

    if (sub == 0) {
        float vlo = 1.0f - __expf(-lo);
        float vhi = 1.0f - __expf(-hi);
        int local = op - op0;
        if (s_seed[local * 2 + 0]) vlo = 1.0f;
        if (s_seed[local * 2 + 1]) vhi = 1.0f;
        int o_lo = op + (op & ~(N - 1));   // (2p)*N + a
        int o_hi = o_lo + N;               // (2p+1)*N + a
        g_pred[o_lo] = vlo;
        g_pred[o_hi] = vhi;
        if (final_out) { final_out[o_lo] = vlo; final_out[o_hi] = vhi; }
    }
}

extern "C" void kernel_launch(void* const* d_in, const int* in_sizes, int n_in,
                              void* d_out, int out_size) {
    const float* preds = (const float*)d_in[0];      // [B, N] fp32
    const float* P = (const float*)d_in[1];          // [N, N] fp32, P[b*N + a]
    const int2* seed = (const int2*)d_in[2];         // [NSEEDS, 2] int32 (b, n)
    int nseeds = in_sizes[2] / 2;
    if (nseeds > 128) nseeds = 128;
    float* out = (float*)d_out;

    dim3 gridA(NTILE, NCHUNK);        // (8, 64) = 512 blocks
    dim3 gridC(8 * NPAIR / 256);      // 512 blocks

    for (int t = 0; t < NITER; t++) {
        propA<<<gridA, BLOCK_A>>>(P, preds, t == 0 ? 1 : 0);
        propC<<<gridC, 256>>>(seed, nseeds, (t == NITER - 1) ? out : nullptr);
    }
}